// round 12
// baseline (speedup 1.0000x reference)
#include <cuda_runtime.h>
#include <stdint.h>

#define NB 32
#define NC 512
#define T_IN 1024
#define T_OUT 4096

#define CPB 16                   // channels per CTA -> grid = 32*32 = 1024 (single wave)
#define NT  256                  // threads per CTA
#define EPT (T_IN / NT)          // durations per thread in the scan = 4
#define NW  (NT / 32)            // warps per CTA = 8

// ---------------------------------------------------------------------------
// Fused kernel: each CTA = (batch, 16-channel group).
//   Phase A: scan this batch's durations and scatter the run-length index
//            map into smem as uint16 (indices < 1024).
//   Phase B: gather enc rows through the smem index map, streaming float4
//            stores. One 16-B index load feeds 8 outputs.
// Durations may be int32 or int64 (JAX x64 ambiguity) — detected on-device:
// int64 LE => all odd 32-bit words of batch-0's row are zero (durations<=4096).
// ---------------------------------------------------------------------------
__global__ __launch_bounds__(NT)
void length_regulate_kernel(const float* __restrict__ enc,
                            const int*   __restrict__ dur32,
                            float*       __restrict__ out) {
    const int groups_per_b = NC / CPB;              // 32
    const int b  = blockIdx.x / groups_per_b;
    const int cg = blockIdx.x % groups_per_b;
    const int tid = threadIdx.x;

    __shared__ unsigned short sidx[T_OUT];          // 8 KB index map (u16)
    __shared__ int wsum[NW];                        // per-warp scan sums

    // ---- dtype detection: OR of odd words in first 2048 int32s ----
    int odd = 0;
#pragma unroll
    for (int i = 0; i < T_IN / NT; ++i)
        odd |= dur32[2 * (i * NT + tid) + 1];
    const bool is32 = __syncthreads_or(odd) != 0;

    // ---- Phase A: scan + scatter ----
    int d[EPT];
    {
        const int j0 = tid * EPT;
        if (is32) {
#pragma unroll
            for (int k = 0; k < EPT; ++k) d[k] = dur32[b * T_IN + j0 + k];
        } else {
#pragma unroll
            for (int k = 0; k < EPT; ++k) d[k] = dur32[(b * T_IN + j0 + k) * 2];
        }
    }
    int tot = 0;
    int pre[EPT];
#pragma unroll
    for (int k = 0; k < EPT; ++k) { pre[k] = tot; tot += d[k]; }

    const int lane = tid & 31;
    const int warp = tid >> 5;

    int incl = tot;
#pragma unroll
    for (int o = 1; o < 32; o <<= 1) {
        int n = __shfl_up_sync(0xffffffffu, incl, o);
        if (lane >= o) incl += n;
    }
    if (lane == 31) wsum[warp] = incl;
    __syncthreads();

    // all 32 lanes of warp 0 participate (partial-warp full-mask shfl hangs)
    if (warp == 0) {
        int w = (lane < NW) ? wsum[lane] : 0;
#pragma unroll
        for (int o = 1; o < 32; o <<= 1) {
            int n = __shfl_up_sync(0xffffffffu, w, o);
            if (lane >= o) w += n;
        }
        if (lane < NW) wsum[lane] = w;
    }
    __syncthreads();

    int base = (incl - tot) + (warp ? wsum[warp - 1] : 0);

    {
        const int j0 = tid * EPT;
#pragma unroll
        for (int k = 0; k < EPT; ++k) {
            const int s = base + pre[k];
            const int e = s + d[k];
            for (int t = s; t < e; ++t) sidx[t] = (unsigned short)(j0 + k);
        }
    }
    __syncthreads();

    // ---- Phase B: gather + streaming stores ----
    const int c0 = cg * CPB;
    const size_t rowbase = (size_t)(b * NC + c0);
    const uint4* __restrict__ si = (const uint4*)sidx;   // 8 u16 per uint4

#pragma unroll
    for (int cc = 0; cc < CPB; ++cc) {
        const float* __restrict__ erow = enc + (rowbase + cc) * T_IN;
        float4*      __restrict__ orow = (float4*)(out + (rowbase + cc) * T_OUT);

#pragma unroll
        for (int it = 0; it < (T_OUT / 8) / NT; ++it) {    // 2 iters
            const int g = it * NT + tid;                   // index-group (8 outputs)
            const uint4 p = si[g];

            float4 o0, o1;
            o0.x = __ldg(erow + (p.x & 0xFFFF));
            o0.y = __ldg(erow + (p.x >> 16));
            o0.z = __ldg(erow + (p.y & 0xFFFF));
            o0.w = __ldg(erow + (p.y >> 16));
            o1.x = __ldg(erow + (p.z & 0xFFFF));
            o1.y = __ldg(erow + (p.z >> 16));
            o1.z = __ldg(erow + (p.w & 0xFFFF));
            o1.w = __ldg(erow + (p.w >> 16));

            __stcs(orow + 2 * g,     o0);
            __stcs(orow + 2 * g + 1, o1);
        }
    }
}

// ---------------------------------------------------------------------------
extern "C" void kernel_launch(void* const* d_in, const int* in_sizes, int n_in,
                              void* d_out, int out_size) {
    const void* enc_p = d_in[0];
    const void* dur_p = d_in[1];
    if (n_in >= 2 && in_sizes[0] == NB * T_IN) {    // durations came first
        dur_p = d_in[0];
        enc_p = d_in[1];
    }
    length_regulate_kernel<<<NB * (NC / CPB), NT>>>(
        (const float*)enc_p, (const int*)dur_p, (float*)d_out);
}